// round 17
// baseline (speedup 1.0000x reference)
#include <cuda_runtime.h>
#include <cuda_bf16.h>
#include <cstdint>
#include <math.h>

#define NP 64
#define MM 512
#define DD 256
#define MARGIN 0.2f
#define GRID_SZ 640
#define NTHR 512

__device__ float  g_psum[NP];
__device__ float  g_pcnt[NP];
__device__ float  g_norm[NP * MM];
__device__ float  g_tsort[(size_t)NP * MM * 16];   // per-anchor sorted C values
__device__ float2 g_tsuf [(size_t)NP * MM * 17];   // per-anchor (suffix sum, count)
__device__ int    g_split[NP * 4];                 // split-data-ready per (p, block)
__device__ int    g_ready[NP * 4];                 // tables-ready per (p, block)
__device__ unsigned int g_ticket;                  // last-CTA-done counter
// pre-split bf16 feature arrays (16 MB each), produced by the diag CTAs
__device__ __align__(16) uint16_t g_hi[(size_t)NP * MM * DD];
__device__ __align__(16) uint16_t g_lo[(size_t)NP * MM * DD];

// off-diagonal tile map (6 tiles of the 4x4 upper triangle)
__constant__ int c_oby[6] = {0,0,0,1,1,2};
__constant__ int c_obx[6] = {1,2,3,2,3,3};

// ---------------------------------------------------------------------------
__device__ __forceinline__ void split2(float x0, float x1, uint32_t& hi, uint32_t& lo) {
    uint32_t h;
    asm("cvt.rn.bf16x2.f32 %0, %1, %2;" : "=r"(h) : "f"(x1), "f"(x0));
    float h0 = __uint_as_float(h << 16);
    float h1 = __uint_as_float(h & 0xFFFF0000u);
    float r0 = x0 - h0, r1 = x1 - h1;
    asm("cvt.rn.bf16x2.f32 %0, %1, %2;" : "=r"(lo) : "f"(r1), "f"(r0));
    hi = h;
}

__device__ __forceinline__ uint32_t smem_u32(const void* p) {
    uint32_t a;
    asm("{ .reg .u64 t; cvta.to.shared.u64 t, %1; cvt.u32.u64 %0, t; }" : "=r"(a) : "l"(p));
    return a;
}

#define MMA16816(c0,c1,c2,c3, a0,a1,a2,a3, b0,b1) \
    asm volatile("mma.sync.aligned.m16n8k16.row.col.f32.bf16.bf16.f32 " \
                 "{%0,%1,%2,%3}, {%4,%5,%6,%7}, {%8,%9}, {%0,%1,%2,%3};" \
                 : "+f"(c0), "+f"(c1), "+f"(c2), "+f"(c3) \
                 : "r"(a0), "r"(a1), "r"(a2), "r"(a3), "r"(b0), "r"(b1))

#define LDSM_X4(r0,r1,r2,r3, addr) \
    asm volatile("ldmatrix.sync.aligned.m8n8.x4.shared.b16 {%0,%1,%2,%3}, [%4];" \
        : "=r"(r0), "=r"(r1), "=r"(r2), "=r"(r3) : "r"(addr))

// SMEM layout (same as R16)
#define LDA 40
#define TILE_B (128 * LDA * 2)        // 10240 per bf16 tile
#define BUF_B  (4 * TILE_B)           // 40960 per buffer (AHI,ALO,BHI,BLO)
#define OFF_SR  0
#define OFF_TR  8704
#define OFF_SC  26112
#define OFF_TC  34816
#define OFF_NRM 81920
#define OFF_RED 82944
#define SMEM_TOTAL 83088

// stage one 128x32 bf16 tile global -> smem via cp.async (one 16B chunk/thread)
__device__ __forceinline__ void stage_tile(
    uint32_t sbase, const uint16_t* __restrict__ gsrc, int k0, int tid)
{
    int row = tid >> 2, c = tid & 3;
    uint32_t sa = sbase + row * (LDA * 2) + (c << 4);
    const void* ga = gsrc + (size_t)row * DD + k0 + (c << 3);
    asm volatile("cp.async.cg.shared.global [%0], [%1], 16;"
                 :: "r"(sa), "l"(ga) : "memory");
}

// 4-step scalar binary search with hoisted S[7]/S[15]; idx in [0,16]
__device__ __forceinline__ void search2(
    const float* __restrict__ S, const float2* __restrict__ T,
    float s7, float s15, float d, float& aA, float& aB, float& aC)
{
    int idx = (s7 <= d) ? 8 : 0;
    idx += (S[idx + 3] <= d) ? 4 : 0;
    idx += (S[idx + 1] <= d) ? 2 : 0;
    idx += (S[idx]     <= d) ? 1 : 0;
    idx = (s15 <= d) ? 16 : idx;
    float2 t = T[idx];
    aA += t.x;
    aB  = fmaf(t.y, d, aB);
    aC += t.y;
}

// one chunk of MMAs (2 k-steps) for the 32x32-per-warp tiling
__device__ __forceinline__ void mma_chunk(
    uint32_t bA, uint32_t bB, int aRowOff, int bRowOff, float c[2][4][4])
{
#pragma unroll
    for (int ks = 0; ks < 2; ks++) {
        const int kOff = ks << 5;
#pragma unroll
        for (int mi = 0; mi < 2; mi++) {
            uint32_t a0, a1, a2, a3, x0, x1, x2, x3;
            uint32_t aa = bA + aRowOff + mi * (16 * LDA * 2) + kOff;
            LDSM_X4(a0, a1, a2, a3, aa);
            LDSM_X4(x0, x1, x2, x3, aa + TILE_B);
#pragma unroll
            for (int n2 = 0; n2 < 2; n2++) {
                uint32_t ba = bB + bRowOff + n2 * (16 * LDA * 2) + kOff;
                uint32_t bh0, bh1, bh2, bh3, bl0, bl1, bl2, bl3;
                LDSM_X4(bh0, bh1, bh2, bh3, ba);
                LDSM_X4(bl0, bl1, bl2, bl3, ba + TILE_B);
                const int n0 = 2 * n2, n1 = n0 + 1;
                MMA16816(c[mi][n0][0], c[mi][n0][1], c[mi][n0][2], c[mi][n0][3],
                         a0, a1, a2, a3, bh0, bh1);
                MMA16816(c[mi][n0][0], c[mi][n0][1], c[mi][n0][2], c[mi][n0][3],
                         a0, a1, a2, a3, bl0, bl1);
                MMA16816(c[mi][n0][0], c[mi][n0][1], c[mi][n0][2], c[mi][n0][3],
                         x0, x1, x2, x3, bh0, bh1);
                MMA16816(c[mi][n1][0], c[mi][n1][1], c[mi][n1][2], c[mi][n1][3],
                         a0, a1, a2, a3, bh2, bh3);
                MMA16816(c[mi][n1][0], c[mi][n1][1], c[mi][n1][2], c[mi][n1][3],
                         a0, a1, a2, a3, bl2, bl3);
                MMA16816(c[mi][n1][0], c[mi][n1][1], c[mi][n1][2], c[mi][n1][3],
                         x0, x1, x2, x3, bh2, bh3);
            }
        }
    }
}

// ---------------------------------------------------------------------------
// single fused kernel. bid<256: diag producer (loads f32, splits inline, writes
// g_hi/g_lo + g_norm, releases g_split, builds tables, releases g_ready).
// bid>=256: off-diag consumer (waits g_split, cp.async pipeline, waits g_ready).
// ---------------------------------------------------------------------------
__global__ void __launch_bounds__(NTHR, 2) fused_kernel(
    const float* __restrict__ feat, float* __restrict__ out, int out_size)
{
    extern __shared__ char smem[];
    const int tid = threadIdx.x;
    const int w = tid >> 5, lane = tid & 31;
    const int g = lane >> 2, tg = lane & 3;
    const int wm = w >> 2, wn = w & 3;
    const int bid = blockIdx.x;
    const bool diag = (bid < 256);
    int p, by, bx;
    if (diag) {
        p = bid >> 2; by = bx = bid & 3;
    } else {
        int q = bid - 256;
        p = q / 6;
        int t = q - p * 6;
        by = c_oby[t]; bx = c_obx[t];
    }
    const uint32_t sb = smem_u32(smem);

    float* sNi = reinterpret_cast<float*>(smem + OFF_NRM);
    float* sNj = diag ? sNi : (sNi + 128);

    // ldmatrix per-lane offsets (bytes within a tile)
    const int aRowOff = ((wm << 5) + (lane & 15)) * (LDA * 2)
                      + ((lane & 16) ? 16 : 0);
    const int bRowOff = ((wn << 5) + (lane & 7) + ((lane & 16) ? 8 : 0)) * (LDA * 2)
                      + ((lane & 8) ? 16 : 0);

    float c[2][4][4];
#pragma unroll
    for (int mi = 0; mi < 2; mi++)
#pragma unroll
        for (int ni = 0; ni < 4; ni++)
#pragma unroll
            for (int r = 0; r < 4; r++) c[mi][ni][r] = 0.f;

    if (diag) {
        // ---- producer path: load f32, split, STS + STG, MMA (single buffer)
        const size_t blkOff = ((size_t)p * MM + (size_t)by * 128) * DD;
        const float* F = feat + blkOff;
        uint16_t* GH = g_hi + blkOff;
        uint16_t* GL = g_lo + blkOff;
        const int row = tid >> 2, c8 = (tid & 3) << 3;
        float nacc = 0.f;
        uint16_t* sH = reinterpret_cast<uint16_t*>(smem);
        uint16_t* sL = reinterpret_cast<uint16_t*>(smem + TILE_B);
        const int sidx = row * LDA + c8;

#pragma unroll 1
        for (int ch = 0; ch < 8; ch++) {
            int k0 = ch << 5;
            const float4* fp = reinterpret_cast<const float4*>(F + (size_t)row * DD + k0 + c8);
            float4 v0 = fp[0], v1 = fp[1];
            nacc = fmaf(v0.x, v0.x, nacc); nacc = fmaf(v0.y, v0.y, nacc);
            nacc = fmaf(v0.z, v0.z, nacc); nacc = fmaf(v0.w, v0.w, nacc);
            nacc = fmaf(v1.x, v1.x, nacc); nacc = fmaf(v1.y, v1.y, nacc);
            nacc = fmaf(v1.z, v1.z, nacc); nacc = fmaf(v1.w, v1.w, nacc);
            uint32_t h0, h1, h2, h3, l0, l1, l2, l3;
            split2(v0.x, v0.y, h0, l0); split2(v0.z, v0.w, h1, l1);
            split2(v1.x, v1.y, h2, l2); split2(v1.z, v1.w, h3, l3);
            uint4 hv = make_uint4(h0, h1, h2, h3);
            uint4 lv = make_uint4(l0, l1, l2, l3);
            *reinterpret_cast<uint4*>(&sH[sidx]) = hv;
            *reinterpret_cast<uint4*>(&sL[sidx]) = lv;
            *reinterpret_cast<uint4*>(GH + (size_t)row * DD + k0 + c8) = hv;
            *reinterpret_cast<uint4*>(GL + (size_t)row * DD + k0 + c8) = lv;
            __syncthreads();
            mma_chunk(sb, sb, aRowOff, bRowOff, c);
            __syncthreads();
        }
        // norms: 4 threads per row (c8 groups) -> shfl over lane bits 0..1
        nacc += __shfl_xor_sync(0xffffffffu, nacc, 1);
        nacc += __shfl_xor_sync(0xffffffffu, nacc, 2);
        if ((lane & 3) == 0) {
            sNi[row] = nacc;
            g_norm[p * MM + by * 128 + row] = nacc;
        }
        __threadfence();
        __syncthreads();   // sNi visible; g_hi/g_lo/g_norm globally ordered
        if (tid == 0)
            asm volatile("st.release.gpu.global.b32 [%0], %1;"
                         :: "l"(&g_split[bid]), "r"(1) : "memory");
    } else {
        // ---- consumer path: wait for both producers' split data
        if (tid == 0) {
            const int* f1 = &g_split[(p << 2) + by];
            const int* f2 = &g_split[(p << 2) + bx];
            int r1, r2;
            while (true) {
                asm volatile("ld.acquire.gpu.global.b32 %0, [%1];" : "=r"(r1) : "l"(f1) : "memory");
                asm volatile("ld.acquire.gpu.global.b32 %0, [%1];" : "=r"(r2) : "l"(f2) : "memory");
                if (r1 && r2) break;
                __nanosleep(128);
            }
        }
        __syncthreads();
        if (tid < 128) {
            sNi[tid] = g_norm[p * MM + by * 128 + tid];
            sNj[tid] = g_norm[p * MM + bx * 128 + tid];
        }
        const size_t Aoff = ((size_t)p * MM + (size_t)by * 128) * DD;
        const size_t Boff = ((size_t)p * MM + (size_t)bx * 128) * DD;
        const uint16_t* Ahi = g_hi + Aoff;
        const uint16_t* Alo = g_lo + Aoff;
        const uint16_t* Bhi = g_hi + Boff;
        const uint16_t* Blo = g_lo + Boff;

        stage_tile(sb, Ahi, 0, tid);
        stage_tile(sb + TILE_B, Alo, 0, tid);
        stage_tile(sb + 2 * TILE_B, Bhi, 0, tid);
        stage_tile(sb + 3 * TILE_B, Blo, 0, tid);
        asm volatile("cp.async.commit_group;" ::: "memory");

#pragma unroll 1
        for (int ch = 0; ch < 8; ch++) {
            if (ch < 7) {
                uint32_t bn = sb + ((ch + 1) & 1) * BUF_B;
                int k1 = (ch + 1) << 5;
                stage_tile(bn, Ahi, k1, tid);
                stage_tile(bn + TILE_B, Alo, k1, tid);
                stage_tile(bn + 2 * TILE_B, Bhi, k1, tid);
                stage_tile(bn + 3 * TILE_B, Blo, k1, tid);
                asm volatile("cp.async.commit_group;" ::: "memory");
                asm volatile("cp.async.wait_group 1;" ::: "memory");
            } else {
                asm volatile("cp.async.wait_group 0;" ::: "memory");
            }
            __syncthreads();
            uint32_t bA = sb + (ch & 1) * BUF_B;
            mma_chunk(bA, bA + 2 * TILE_B, aRowOff, bRowOff, c);
            __syncthreads();
        }
    }

    // distances in place of accumulators
#pragma unroll
    for (int mi = 0; mi < 2; mi++) {
        int i0 = (wm << 5) + (mi << 4) + g;
#pragma unroll
        for (int ni = 0; ni < 4; ni++) {
            int j0 = (wn << 5) + (ni << 3) + (tg << 1);
            c[mi][ni][0] = sqrtf(fmaxf(sNi[i0]     + sNj[j0]     - 2.f * c[mi][ni][0], 0.f));
            c[mi][ni][1] = sqrtf(fmaxf(sNi[i0]     + sNj[j0 + 1] - 2.f * c[mi][ni][1], 0.f));
            c[mi][ni][2] = sqrtf(fmaxf(sNi[i0 + 8] + sNj[j0]     - 2.f * c[mi][ni][2], 0.f));
            c[mi][ni][3] = sqrtf(fmaxf(sNi[i0 + 8] + sNj[j0 + 1] - 2.f * c[mi][ni][3], 0.f));
        }
    }

    float*  sSR = reinterpret_cast<float*>(smem + OFF_SR);   // stride 17
    float2* sTR = reinterpret_cast<float2*>(smem + OFF_TR);  // stride 17
    float*  sSC = reinterpret_cast<float*>(smem + OFF_SC);   // stride 17
    float2* sTC = reinterpret_cast<float2*>(smem + OFF_TC);  // stride 17

    if (diag) {
        // scatter same-class C values (classes are 16-aligned: class = idx>>4)
        float* sPos = reinterpret_cast<float*>(smem + OFF_SC);
#pragma unroll
        for (int mi = 0; mi < 2; mi++) {
            int ia = (wm << 5) + (mi << 4) + g, ib = ia + 8;
#pragma unroll
            for (int ni = 0; ni < 4; ni++) {
                int j0 = (wn << 5) + (ni << 3) + (tg << 1);
#pragma unroll
                for (int e = 0; e < 2; e++) {
                    int j = j0 + e;
                    if ((ia >> 4) == (j >> 4)) sPos[(ia << 4) + (j & 15)] = MARGIN + c[mi][ni][e];
                    if ((ib >> 4) == (j >> 4)) sPos[(ib << 4) + (j & 15)] = MARGIN + c[mi][ni][2 + e];
                }
            }
        }
        __syncthreads();
        if (tid < 128) {
            float v[16];
#pragma unroll
            for (int k = 0; k < 16; k++) v[k] = sPos[(tid << 4) + k];
            float* ss = &sSR[tid * 17];
#pragma unroll
            for (int k = 0; k < 16; k++) {
                float vk = v[k];
                int r = 0;
#pragma unroll
                for (int jj = 0; jj < 16; jj++)
                    r += (int)((v[jj] < vk) | ((v[jj] == vk) & (jj < k)));
                ss[r] = vk;
            }
            size_t ab = (size_t)p * MM + by * 128 + tid;
            float run = 0.f;
            sTR[tid * 17 + 16] = make_float2(0.f, 0.f);
            g_tsuf[ab * 17 + 16] = make_float2(0.f, 0.f);
#pragma unroll
            for (int k = 15; k >= 0; k--) {
                run += ss[k];
                float2 tv = make_float2(run, (float)(16 - k));
                sTR[tid * 17 + k] = tv;
                g_tsuf[ab * 17 + k] = tv;
                g_tsort[ab * 16 + k] = ss[k];
            }
        }
        __threadfence();
        __syncthreads();
        if (tid == 0)
            asm volatile("st.release.gpu.global.b32 [%0], %1;"
                         :: "l"(&g_ready[bid]), "r"(1) : "memory");
    } else {
        if (tid == 0) {
            const int* f1 = &g_ready[(p << 2) + by];
            const int* f2 = &g_ready[(p << 2) + bx];
            int r1, r2;
            while (true) {
                asm volatile("ld.acquire.gpu.global.b32 %0, [%1];" : "=r"(r1) : "l"(f1) : "memory");
                asm volatile("ld.acquire.gpu.global.b32 %0, [%1];" : "=r"(r2) : "l"(f2) : "memory");
                if (r1 && r2) break;
                __nanosleep(128);
            }
        }
        __syncthreads();
        size_t rb16 = ((size_t)p * MM + by * 128) * 16;
        size_t rb17 = ((size_t)p * MM + by * 128) * 17;
        size_t cb16 = ((size_t)p * MM + bx * 128) * 16;
        size_t cb17 = ((size_t)p * MM + bx * 128) * 17;
        for (int q = tid; q < 2048; q += NTHR) {
            sSR[(q >> 4) * 17 + (q & 15)] = g_tsort[rb16 + q];
            sSC[(q >> 4) * 17 + (q & 15)] = g_tsort[cb16 + q];
        }
        for (int q = tid; q < 2176; q += NTHR) {
            sTR[q] = g_tsuf[rb17 + q];
            sTC[q] = g_tsuf[cb17 + q];
        }
        __syncthreads();
    }

    // hinge searches
    const int abase = wm << 5;
    int aIdx[4] = {abase + g, abase + g + 8, abase + 16 + g, abase + 24 + g};
    const float*  SR[4]; const float2* TR[4];
    float S7[4], S15[4];
#pragma unroll
    for (int q = 0; q < 4; q++) {
        SR[q]  = &sSR[aIdx[q] * 17];
        TR[q]  = &sTR[aIdx[q] * 17];
        S7[q]  = SR[q][7];
        S15[q] = SR[q][15];
    }
    float aA = 0.f, aB = 0.f, aC = 0.f;
#pragma unroll
    for (int ni = 0; ni < 4; ni++) {
#pragma unroll
        for (int e = 0; e < 2; e++) {
            int j = (wn << 5) + (ni << 3) + (tg << 1) + e;
            float c7 = 0.f, c15 = 0.f;
            const float* SCj = &sSC[j * 17];
            const float2* TCj = &sTC[j * 17];
            if (!diag) { c7 = SCj[7]; c15 = SCj[15]; }
            int jc = j >> 4;
#pragma unroll
            for (int mi = 0; mi < 2; mi++) {
                float d0 = c[mi][ni][e];
                float d1 = c[mi][ni][2 + e];
                const int q0 = mi << 1, q1 = q0 + 1;
                bool ok0 = !diag || ((aIdx[q0] >> 4) != jc);
                bool ok1 = !diag || ((aIdx[q1] >> 4) != jc);
                if (ok0) search2(SR[q0], TR[q0], S7[q0], S15[q0], d0, aA, aB, aC);
                if (ok1) search2(SR[q1], TR[q1], S7[q1], S15[q1], d1, aA, aB, aC);
                if (!diag) {
                    search2(SCj, TCj, c7, c15, d0, aA, aB, aC);
                    search2(SCj, TCj, c7, c15, d1, aA, aB, aC);
                }
            }
        }
    }

    float loss = aA - aB, cnt = aC;
#pragma unroll
    for (int o = 16; o; o >>= 1) {
        loss += __shfl_xor_sync(0xffffffffu, loss, o);
        cnt  += __shfl_xor_sync(0xffffffffu, cnt, o);
    }
    float* sRed = reinterpret_cast<float*>(smem + OFF_RED);
    int*   sFlag = reinterpret_cast<int*>(smem + OFF_RED + 128);
    if (lane == 0) { sRed[w] = loss; sRed[16 + w] = cnt; }
    __syncthreads();
    if (tid == 0) {
        float L = 0.f, C = 0.f;
#pragma unroll
        for (int k = 0; k < 16; k++) { L += sRed[k]; C += sRed[16 + k]; }
        atomicAdd(&g_psum[p], L);
        atomicAdd(&g_pcnt[p], C);
        __threadfence();
        unsigned int t = atomicAdd(&g_ticket, 1u);
        *sFlag = (t == GRID_SZ - 1u);
    }
    __syncthreads();

    // last CTA: final reduce + write output + reset state for next launch
    if (*sFlag) {
        __threadfence();
        float a = 0.f, b = 0.f;
        if (tid < NP) {
            float cc = g_pcnt[tid], ssum = g_psum[tid];
            a = (cc > 0.f) ? ssum / fmaxf(cc, 1.f) : 0.f;
            b = cc;
        }
#pragma unroll
        for (int o = 16; o; o >>= 1) {
            a += __shfl_xor_sync(0xffffffffu, a, o);
            b += __shfl_xor_sync(0xffffffffu, b, o);
        }
        if (lane == 0 && w < 2) { sRed[w] = a; sRed[2 + w] = b; }
        __syncthreads();
        if (tid == 0) {
            out[0] = (sRed[0] + sRed[1]) / (float)NP;
            if (out_size > 1) out[1] = (sRed[2] + sRed[3]) / (float)NP;
            g_ticket = 0;
        }
        if (tid < NP) { g_psum[tid] = 0.f; g_pcnt[tid] = 0.f; }
        if (tid < NP * 4) { g_ready[tid] = 0; g_split[tid] = 0; }
    }
}

extern "C" void kernel_launch(void* const* d_in, const int* in_sizes, int n_in,
                              void* d_out, int out_size) {
    const float* feat = (const float*)d_in[0];
    (void)in_sizes; (void)n_in;

    cudaFuncSetAttribute(fused_kernel, cudaFuncAttributeMaxDynamicSharedMemorySize, SMEM_TOTAL);

    fused_kernel<<<GRID_SZ, NTHR, SMEM_TOTAL>>>(feat, (float*)d_out, out_size);
}